// round 12
// baseline (speedup 1.0000x reference)
#include <cuda_runtime.h>

// reshape_78271484002964: [16,64,256,256] f32, SPLIT=(2,16,16), map_type=1.
// out[b,i,j,k,cc,hh,ww] = in[b,i,cc,j,hh,k,ww]
// sizes: b=16, i=2, j=16, k=16, cc=32, hh=16, ww=16.
//
// float4-unit bit maps (24 bits).
// Input m (fast->slow):  ww4 [0,2) | k [2,6) | hh [6,10) | j [10,14)
//                        | cc [14,19) | i 19 | b [20,24)
// Output g (fast->slow): ww4 [0,2) | hh [2,6) | cc [6,11) | k [11,15)
//                        | j [15,19) | i 19 | b [20,24)
//
// R12: PERSISTENT grid-stride version of R11 (16 float4/thread tiles).
// grid = 444 CTAs (148 SMs x 3 resident at 74 regs) -> zero wave
// transitions; each CTA loops over tiles, so the next iteration's 16 loads
// issue immediately behind the current stores, keeping DRAM pressure
// continuous instead of sawtoothing across ~9 waves.
// Per-tile structure identical to R11 (best ncu time / 82.0% DRAM):
//   loads:  warp = 512 B contiguous, 16 per thread (MLP=16)
//   stores: 64 B granules, L2-merged (proven fine R8/R10/R11)

__device__ __forceinline__ unsigned in_to_out(unsigned m) {
    return  (m & 3u)                      // ww4
         | (((m >> 6)  & 15u) << 2)       // hh
         | (((m >> 14) & 31u) << 6)       // cc
         | (((m >> 2)  & 15u) << 11)      // k
         | (((m >> 10) & 15u) << 15)      // j
         |  (m & 0xFFF80000u);            // i, b pass through
}

#define NUM_TILES 4096u   // 16,777,216 float4 / (256 thr * 16 f4)

__global__ void __launch_bounds__(256)
reshape_78271484002964_kernel(const float4* __restrict__ in,
                              float4* __restrict__ out) {
    const unsigned tid  = threadIdx.x;
    const unsigned step = gridDim.x;

    for (unsigned t = blockIdx.x; t < NUM_TILES; t += step) {
        const unsigned m0   = t * 4096u + tid;
        const unsigned out0 = in_to_out(m0);

        float4 v[16];
#pragma unroll
        for (int q = 0; q < 16; q++)
            v[q] = __ldcs(in + m0 + (unsigned)q * 256u);

#pragma unroll
        for (int q = 0; q < 16; q++)
            __stcs(out + out0 + (unsigned)(q & 3) * 16u
                              + (unsigned)((q >> 2) & 1) * 32768u
                              + (unsigned)(q >> 3) * 65536u, v[q]);
    }
}

extern "C" void kernel_launch(void* const* d_in, const int* in_sizes, int n_in,
                              void* d_out, int out_size) {
    const float4* in  = (const float4*)d_in[0];
    float4*       out = (float4*)d_out;
    // Persistent: 148 SMs x 3 CTAs resident (74-reg limit) = 444 CTAs.
    reshape_78271484002964_kernel<<<444, 256>>>(in, out);
}

// round 13
// speedup vs baseline: 1.1231x; 1.1231x over previous
#include <cuda_runtime.h>

// reshape_78271484002964: [16,64,256,256] f32, SPLIT=(2,16,16), map_type=1.
// out[b,i,j,k,cc,hh,ww] = in[b,i,cc,j,hh,k,ww]
// sizes: b=16, i=2, j=16, k=16, cc=32, hh=16, ww=16.
//
// float4-unit bit maps (24 bits).
// Input m (fast->slow):  ww4 [0,2) | k [2,6) | hh [6,10) | j [10,14)
//                        | cc [14,19) | i 19 | b [20,24)
// Output g (fast->slow): ww4 [0,2) | hh [2,6) | cc [6,11) | k [11,15)
//                        | j [15,19) | i 19 | b [20,24)
//
// R13: exactly the R11 structure (best so far: ncu 74.75us, DRAM 82.0%) —
// input-order, 16 float4/thread (MLP=16), 4096 independent blocks — with
// stores switched to __stwt (write-through). Rationale: default/.cs stores
// make L2 absorb 512MB of dirty lines and write them back in bursty
// contention with the demand reads; .wt streams writes through to the
// memory controller at a steady pace (full 32B sectors, no RMW), cutting
// read/write turnaround clustering and L2 double-handling.

__device__ __forceinline__ unsigned in_to_out(unsigned m) {
    return  (m & 3u)                      // ww4
         | (((m >> 6)  & 15u) << 2)       // hh
         | (((m >> 14) & 31u) << 6)       // cc
         | (((m >> 2)  & 15u) << 11)      // k
         | (((m >> 10) & 15u) << 15)      // j
         |  (m & 0xFFF80000u);            // i, b pass through
}

__global__ void __launch_bounds__(256)
reshape_78271484002964_kernel(const float4* __restrict__ in,
                              float4* __restrict__ out) {
    const unsigned m0   = blockIdx.x * 4096u + threadIdx.x;
    const unsigned out0 = in_to_out(m0);

    float4 v[16];
#pragma unroll
    for (int q = 0; q < 16; q++)
        v[q] = __ldcs(in + m0 + (unsigned)q * 256u);

#pragma unroll
    for (int q = 0; q < 16; q++)
        __stwt(out + out0 + (unsigned)(q & 3) * 16u
                          + (unsigned)((q >> 2) & 1) * 32768u
                          + (unsigned)(q >> 3) * 65536u, v[q]);
}

extern "C" void kernel_launch(void* const* d_in, const int* in_sizes, int n_in,
                              void* d_out, int out_size) {
    const float4* in  = (const float4*)d_in[0];
    float4*       out = (float4*)d_out;
    // 16,777,216 float4 / 4096 per block = 4096 blocks
    reshape_78271484002964_kernel<<<4096, 256>>>(in, out);
}

// round 14
// speedup vs baseline: 1.1368x; 1.0122x over previous
#include <cuda_runtime.h>

// reshape_78271484002964: [16,64,256,256] f32, SPLIT=(2,16,16), map_type=1.
// out[b,i,j,k,cc,hh,ww] = in[b,i,cc,j,hh,k,ww]
// sizes: b=16, i=2, j=16, k=16, cc=32, hh=16, ww=16.
//
// float4-unit bit maps (24 bits).
// Input m (fast->slow):  ww4 [0,2) | k [2,6) | hh [6,10) | j [10,14)
//                        | cc [14,19) | i 19 | b [20,24)
// Output g (fast->slow): ww4 [0,2) | hh [2,6) | cc [6,11) | k [11,15)
//                        | j [15,19) | i 19 | b [20,24)
//
// R14: R11 structure (best: ncu 74.75us / DRAM 82.0%) + BLOCK-INDEX SWIZZLE
// for cross-CTA write locality. Tile index t (= m >> 12) bits:
//   t[0:2) = j2,j3 | t[2:7) = cc | t[7] = i | t[8:12) = b
// Remap bid -> t so consecutive bids vary cc first:
//   t = (bid[0:5) << 2) | bid[5:7) | (bid[7:12) << 7)
// => any 32 consecutive (co-resident) CTAs write one DENSE contiguous 2MB
// output region (out bits 0-16 fully tiled) instead of sparse 1KB runs over
// several windows -> better DRAM row-buffer locality on the write stream.
// Reads: each CTA still reads one contiguous 64KB chunk (unaffected).

__device__ __forceinline__ unsigned in_to_out(unsigned m) {
    return  (m & 3u)                      // ww4
         | (((m >> 6)  & 15u) << 2)       // hh
         | (((m >> 14) & 31u) << 6)       // cc
         | (((m >> 2)  & 15u) << 11)      // k
         | (((m >> 10) & 15u) << 15)      // j
         |  (m & 0xFFF80000u);            // i, b pass through
}

__global__ void __launch_bounds__(256)
reshape_78271484002964_kernel(const float4* __restrict__ in,
                              float4* __restrict__ out) {
    const unsigned bid = blockIdx.x;
    // bid -> tile index: cc in low bid bits, j2j3 next, i/b pass through.
    const unsigned t = ((bid & 31u) << 2)      // cc  -> t[2:7)
                     | ((bid >> 5) & 3u)       // j2,j3 -> t[0:2)
                     | ((bid >> 7) << 7);      // i, b -> t[7:12)

    const unsigned m0   = t * 4096u + threadIdx.x;
    const unsigned out0 = in_to_out(m0);

    float4 v[16];
#pragma unroll
    for (int q = 0; q < 16; q++)
        v[q] = __ldcs(in + m0 + (unsigned)q * 256u);

#pragma unroll
    for (int q = 0; q < 16; q++)
        __stcs(out + out0 + (unsigned)(q & 3) * 16u
                          + (unsigned)((q >> 2) & 1) * 32768u
                          + (unsigned)(q >> 3) * 65536u, v[q]);
}

extern "C" void kernel_launch(void* const* d_in, const int* in_sizes, int n_in,
                              void* d_out, int out_size) {
    const float4* in  = (const float4*)d_in[0];
    float4*       out = (float4*)d_out;
    // 16,777,216 float4 / 4096 per block = 4096 blocks
    reshape_78271484002964_kernel<<<4096, 256>>>(in, out);
}